// round 11
// baseline (speedup 1.0000x reference)
#include <cuda_runtime.h>
#include <math.h>
#include <stdint.h>

// Problem constants
#define NTOK 32768      // 8 * 4096 tokens
#define DIN  1536       // D + DC
#define DH   3072       // 2 * din
#define NE   64         // experts
#define DI   1024       // D
#define DCND 512        // DC

// GEMM1 tiling: CTA 128 tokens x 128 hcols, K-chunk 32
#define KC     32
#define NCHUNK (DIN / KC)        // 48
#define SSTR   36                // raw smem row stride (floats); bank = 4*gID+tig, conflict-free
#define TILE_F (128 * SSTR)      // 4608 floats per matrix
#define STAGE_F (2 * TILE_F)     // A then B: 9216 floats per stage
#define SMEM1_BYTES (2 * STAGE_F * 4)   // 73728 B

// Scratch for h = gelu(X @ W1^T): 32768 x 3072 fp32 = 402 MB
static __device__ float g_h[(size_t)NTOK * DH];

__device__ __forceinline__ float gelu_exact(float x) {
    return 0.5f * x * (1.0f + erff(x * 0.7071067811865475f));
}

// Round to tf32 (RNA): hi, and tf32-rounded residual lo.
__device__ __forceinline__ void tf32_split(float x, uint32_t& h, uint32_t& l) {
    uint32_t t;
    asm("cvt.rna.tf32.f32 %0, %1;" : "=r"(t) : "f"(x));
    h = t;
    float r = x - __uint_as_float(t);
    asm("cvt.rna.tf32.f32 %0, %1;" : "=r"(t) : "f"(r));
    l = t;
}

__device__ __forceinline__ void mma1688(float c[4], const uint32_t a[4],
                                        uint32_t b0, uint32_t b1) {
    asm volatile(
        "mma.sync.aligned.m16n8k8.row.col.f32.tf32.tf32.f32 "
        "{%0,%1,%2,%3}, {%4,%5,%6,%7}, {%8,%9}, {%0,%1,%2,%3};"
        : "+f"(c[0]), "+f"(c[1]), "+f"(c[2]), "+f"(c[3])
        : "r"(a[0]), "r"(a[1]), "r"(a[2]), "r"(a[3]), "r"(b0), "r"(b1));
}

// cp.async one K-chunk (raw fp32) into stage: A[128][36], B[128][36]
__device__ __forceinline__ void cp_chunk(
    float* st, int c, int tid, int nblk, int mblk,
    const float* __restrict__ inp, const float* __restrict__ cnd,
    const float* __restrict__ W1)
{
    const int kbase = c * KC;
    const uint32_t sA = (uint32_t)__cvta_generic_to_shared(st);
    const uint32_t sB = sA + TILE_F * 4;
#pragma unroll
    for (int it = 0; it < 4; ++it) {
        const int idx = tid + it * 256;
        const int row = idx >> 3, c8 = idx & 7;   // 8 x 16B granules per 32-float row
        const int kk = kbase + c8 * 4;
        const float* ag = (kk < DI)
            ? inp + (size_t)(nblk + row) * DI   + kk
            : cnd + (size_t)(nblk + row) * DCND + (kk - DI);
        const float* bg = W1 + (size_t)(mblk + row) * DIN + kk;
        const uint32_t off = (uint32_t)(row * SSTR + c8 * 4) * 4;
        asm volatile("cp.async.cg.shared.global [%0], [%1], 16;" :: "r"(sA + off), "l"(ag));
        asm volatile("cp.async.cg.shared.global [%0], [%1], 16;" :: "r"(sB + off), "l"(bg));
    }
}

// ---------------------------------------------------------------------------
// GEMM1 (mma.sync tf32, 3xTF32, split-at-consume): g_h = gelu(X @ W1^T)
// ---------------------------------------------------------------------------
extern "C" __global__ void __launch_bounds__(256, 1)
k_gemm1_mma(const float* __restrict__ inp,
            const float* __restrict__ cnd,
            const float* __restrict__ W1)
{
    extern __shared__ float sm[];

    const int tid  = threadIdx.x;
    const int lane = tid & 31;
    const int wid  = tid >> 5;
    const int wm   = wid & 1;          // 0..1 : 64-token half
    const int wn   = wid >> 1;         // 0..3 : 32-hcol slice
    const int gID  = lane >> 2;        // 0..7
    const int tig  = lane & 3;         // 0..3
    const int mblk = blockIdx.x * 128; // hcol base
    const int nblk = blockIdx.y * 128; // token base

    float acc[4][4][4];
#pragma unroll
    for (int mt = 0; mt < 4; mt++)
#pragma unroll
        for (int nt = 0; nt < 4; nt++)
#pragma unroll
            for (int q = 0; q < 4; q++) acc[mt][nt][q] = 0.f;

    // prologue: chunk 0 -> stage 0
    cp_chunk(sm, 0, tid, nblk, mblk, inp, cnd, W1);
    asm volatile("cp.async.commit_group;" ::: "memory");

    for (int c = 0; c < NCHUNK; ++c) {
        const int buf = c & 1;
        if (c + 1 < NCHUNK) {
            cp_chunk(sm + ((c + 1) & 1) * STAGE_F, c + 1, tid, nblk, mblk, inp, cnd, W1);
            asm volatile("cp.async.commit_group;" ::: "memory");
            asm volatile("cp.async.wait_group 1;" ::: "memory");  // stage[buf] ready
        } else {
            asm volatile("cp.async.wait_group 0;" ::: "memory");
        }
        __syncthreads();

        const float* sA = sm + buf * STAGE_F;
        const float* sB = sA + TILE_F;
#pragma unroll
        for (int ks = 0; ks < 4; ++ks) {
            const int kk = ks * 8 + tig;
            uint32_t ahi[4][4], alo[4][4], bhi[4][2], blo[4][2];
#pragma unroll
            for (int mt = 0; mt < 4; ++mt) {
                const int r0 = wm * 64 + mt * 16 + gID;
                float v0 = sA[r0 * SSTR + kk];
                float v1 = sA[(r0 + 8) * SSTR + kk];
                float v2 = sA[r0 * SSTR + kk + 4];
                float v3 = sA[(r0 + 8) * SSTR + kk + 4];
                tf32_split(v0, ahi[mt][0], alo[mt][0]);
                tf32_split(v1, ahi[mt][1], alo[mt][1]);
                tf32_split(v2, ahi[mt][2], alo[mt][2]);
                tf32_split(v3, ahi[mt][3], alo[mt][3]);
            }
#pragma unroll
            for (int nt = 0; nt < 4; ++nt) {
                const int nr = wn * 32 + nt * 8 + gID;
                float v0 = sB[nr * SSTR + kk];
                float v1 = sB[nr * SSTR + kk + 4];
                tf32_split(v0, bhi[nt][0], blo[nt][0]);
                tf32_split(v1, bhi[nt][1], blo[nt][1]);
            }
            // pass-major: 16 independent accumulators between reuses
#pragma unroll
            for (int mt = 0; mt < 4; ++mt)
#pragma unroll
                for (int nt = 0; nt < 4; ++nt)
                    mma1688(acc[mt][nt], ahi[mt], bhi[nt][0], bhi[nt][1]);  // hi*hi
#pragma unroll
            for (int mt = 0; mt < 4; ++mt)
#pragma unroll
                for (int nt = 0; nt < 4; ++nt)
                    mma1688(acc[mt][nt], ahi[mt], blo[nt][0], blo[nt][1]);  // hi*lo
#pragma unroll
            for (int mt = 0; mt < 4; ++mt)
#pragma unroll
                for (int nt = 0; nt < 4; ++nt)
                    mma1688(acc[mt][nt], alo[mt], bhi[nt][0], bhi[nt][1]);  // lo*hi
        }
        __syncthreads();   // done reading stage[buf] before it is overwritten
    }

    // ---- epilogue: GELU + store to g_h ----
#pragma unroll
    for (int mt = 0; mt < 4; ++mt) {
        const int row0 = nblk + wm * 64 + mt * 16 + gID;
#pragma unroll
        for (int nt = 0; nt < 4; ++nt) {
            const int col = mblk + wn * 32 + nt * 8 + tig * 2;
            float2 v0, v1;
            v0.x = gelu_exact(acc[mt][nt][0]);
            v0.y = gelu_exact(acc[mt][nt][1]);
            v1.x = gelu_exact(acc[mt][nt][2]);
            v1.y = gelu_exact(acc[mt][nt][3]);
            *(float2*)(g_h + (size_t)row0 * DH + col)       = v0;
            *(float2*)(g_h + (size_t)(row0 + 8) * DH + col) = v1;
        }
    }
}

// ---------------------------------------------------------------------------
// Kernel 2 (unchanged, passing): logits + softmax + top-2 + outputs
// ---------------------------------------------------------------------------
__global__ __launch_bounds__(256, 2)
void k_gemm2(const float* __restrict__ W2, float* __restrict__ out)
{
    __shared__ float As[2][8][132];
    __shared__ float Bs[2][8][68];
    __shared__ float lg[128][65];

    const int nblk = blockIdx.x * 128;
    const int tid  = threadIdx.x;
    const int tx   = tid & 15;
    const int ty   = tid >> 4;
    const int lrow = tid >> 1;
    const int lk4  = (tid & 1) << 2;

    float acc[8][4];
#pragma unroll
    for (int i = 0; i < 8; i++)
#pragma unroll
        for (int j = 0; j < 4; j++) acc[i][j] = 0.f;

    const size_t arow = (size_t)(nblk + lrow) * DH;
    const int    erow = tid >> 1;
    const size_t brow = (size_t)erow * DH;

    float4 av, bv;
    av = *(const float4*)(g_h + arow + lk4);
    if (tid < 128) bv = *(const float4*)(W2 + brow + lk4);
    As[0][lk4+0][lrow] = av.x; As[0][lk4+1][lrow] = av.y;
    As[0][lk4+2][lrow] = av.z; As[0][lk4+3][lrow] = av.w;
    if (tid < 128) {
        Bs[0][lk4+0][erow] = bv.x; Bs[0][lk4+1][erow] = bv.y;
        Bs[0][lk4+2][erow] = bv.z; Bs[0][lk4+3][erow] = bv.w;
    }
    __syncthreads();

    int buf = 0;
    for (int k0 = 8; k0 <= DH; k0 += 8) {
        if (k0 < DH) {
            av = *(const float4*)(g_h + arow + k0 + lk4);
            if (tid < 128) bv = *(const float4*)(W2 + brow + k0 + lk4);
        }
#pragma unroll
        for (int k = 0; k < 8; k++) {
            float4 a0 = *(const float4*)&As[buf][k][ty*8];
            float4 a1 = *(const float4*)&As[buf][k][ty*8+4];
            float4 b0 = *(const float4*)&Bs[buf][k][tx*4];
            float a[8] = {a0.x,a0.y,a0.z,a0.w,a1.x,a1.y,a1.z,a1.w};
            float b[4] = {b0.x,b0.y,b0.z,b0.w};
#pragma unroll
            for (int i = 0; i < 8; i++)
#pragma unroll
                for (int j = 0; j < 4; j++)
                    acc[i][j] = fmaf(a[i], b[j], acc[i][j]);
        }
        if (k0 < DH) {
            const int nb = buf ^ 1;
            As[nb][lk4+0][lrow] = av.x; As[nb][lk4+1][lrow] = av.y;
            As[nb][lk4+2][lrow] = av.z; As[nb][lk4+3][lrow] = av.w;
            if (tid < 128) {
                Bs[nb][lk4+0][erow] = bv.x; Bs[nb][lk4+1][erow] = bv.y;
                Bs[nb][lk4+2][erow] = bv.z; Bs[nb][lk4+3][erow] = bv.w;
            }
            buf = nb;
        }
        __syncthreads();
    }

#pragma unroll
    for (int i = 0; i < 8; i++)
#pragma unroll
        for (int j = 0; j < 4; j++)
            lg[ty*8+i][tx*4+j] = acc[i][j];
    __syncthreads();

    if (tid < 128) {
        const int r = tid;
        const int n = nblk + r;

        float m1 = -1e30f; int i1 = 0;
#pragma unroll
        for (int e = 0; e < NE; e++) {
            float v = lg[r][e];
            if (v > m1) { m1 = v; i1 = e; }
        }
        float m2 = -1e30f; int i2 = 0;
#pragma unroll
        for (int e = 0; e < NE; e++) {
            if (e == i1) continue;
            float v = lg[r][e];
            if (v > m2) { m2 = v; i2 = e; }
        }
        float s = 0.f;
#pragma unroll
        for (int e = 0; e < NE; e++) s += expf(lg[r][e] - m1);
        const float inv = 1.0f / s;

        const float lo = 1e-9f, hi = 1.0f - 1e-9f;
        const float p1 = fminf(fmaxf(inv + lo, lo), hi);
        const float p2 = fminf(fmaxf(expf(m2 - m1) * inv + lo, lo), hi);
        const float rn = 1.0f / (p1 + p2);

        float* mask = out;
        float* ti   = out + (size_t)NTOK * NE;
        float* rp   = out + (size_t)NTOK * NE + (size_t)NTOK * 2;
        float* pr   = rp  + (size_t)NTOK * NE;

#pragma unroll
        for (int e = 0; e < NE; e++) {
            float v = expf(lg[r][e] - m1) * inv + lo;
            v = fminf(fmaxf(v, lo), hi);
            pr[(size_t)n * NE + e]   = v;
            mask[(size_t)n * NE + e] = (e == i1 || e == i2) ? 1.0f : 0.0f;
            rp[(size_t)n * NE + e]   = (e == i1) ? p1 * rn
                                     : (e == i2) ? p2 * rn : 0.0f;
        }
        ti[(size_t)n * 2 + 0] = (float)i1;
        ti[(size_t)n * 2 + 1] = (float)i2;
    }
}

// ---------------------------------------------------------------------------
extern "C" void kernel_launch(void* const* d_in, const int* in_sizes, int n_in,
                              void* d_out, int out_size)
{
    const float* inp = (const float*)d_in[0];   // [8,4096,1024]
    const float* cnd = (const float*)d_in[1];   // [8,4096,512]
    const float* W1  = (const float*)d_in[2];   // [3072,1536]
    const float* W2  = (const float*)d_in[3];   // [64,3072]
    float* out = (float*)d_out;

    cudaFuncSetAttribute(k_gemm1_mma, cudaFuncAttributeMaxDynamicSharedMemorySize, SMEM1_BYTES);

    dim3 g1(DH / 128, NTOK / 128);   // 24 x 256 CTAs
    k_gemm1_mma<<<g1, 256, SMEM1_BYTES>>>(inp, cnd, W1);
    k_gemm2<<<NTOK / 128, 256>>>(W2, out);
}